// round 17
// baseline (speedup 1.0000x reference)
#include <cuda_runtime.h>
#include <cuda_fp16.h>

#define TOKENS 100352   // 256 windows * 392 tokens

__device__ __half  g_qkvh[(size_t)TOKENS * 384]; // [token][384] fp16: q*scale*log2e | k | v
__device__ __half  g_atth[(size_t)TOKENS * 128]; // attention out fp16, token-major
__device__ float4  g_rpbT[4 * 25 * 50 * 32];     // frag-ordered rel-pos bias * log2e (+pad jt)
__device__ float   g_qwr[384 * 128];             // rna-rounded qkv weight (fp32/tf32)
__device__ __half  g_pwrh[128 * 128];            // fp16 proj weight

__device__ __forceinline__ unsigned rna(float f) {
    unsigned u; asm("cvt.rna.tf32.f32 %0, %1;" : "=r"(u) : "f"(f)); return u;
}
__device__ __forceinline__ float u2f(unsigned u) { return __uint_as_float(u); }
__device__ __forceinline__ unsigned h2u(float a, float b) {
    __half2 h = __floats2half2_rn(a, b);
    return *(unsigned*)&h;
}
__device__ __forceinline__ unsigned ex2h2(unsigned x) {
    unsigned r; asm("ex2.approx.f16x2 %0, %1;" : "=r"(r) : "r"(x)); return r;
}
__device__ __forceinline__ void mma8(float* d, const unsigned* a, const unsigned* b) {
    asm volatile("mma.sync.aligned.m16n8k8.row.col.f32.tf32.tf32.f32 "
        "{%0,%1,%2,%3}, {%4,%5,%6,%7}, {%8,%9}, {%0,%1,%2,%3};"
        : "+f"(d[0]), "+f"(d[1]), "+f"(d[2]), "+f"(d[3])
        : "r"(a[0]), "r"(a[1]), "r"(a[2]), "r"(a[3]), "r"(b[0]), "r"(b[1]));
}
__device__ __forceinline__ void mmah(float* d, const unsigned* a, const unsigned* b) {
    asm volatile("mma.sync.aligned.m16n8k16.row.col.f32.f16.f16.f32 "
        "{%0,%1,%2,%3}, {%4,%5,%6,%7}, {%8,%9}, {%0,%1,%2,%3};"
        : "+f"(d[0]), "+f"(d[1]), "+f"(d[2]), "+f"(d[3])
        : "r"(a[0]), "r"(a[1]), "r"(a[2]), "r"(a[3]), "r"(b[0]), "r"(b[1]));
}
__device__ __forceinline__ void ldsm4(unsigned* r, unsigned a) {
    asm volatile("ldmatrix.sync.aligned.m8n8.x4.shared.b16 {%0,%1,%2,%3},[%4];"
        : "=r"(r[0]), "=r"(r[1]), "=r"(r[2]), "=r"(r[3]) : "r"(a));
}
__device__ __forceinline__ unsigned sptr(const void* p) {
    return (unsigned)__cvta_generic_to_shared(p);
}
__device__ __forceinline__ void cpa16(unsigned dst, const void* src) {
    asm volatile("cp.async.cg.shared.global [%0],[%1],16;" :: "r"(dst), "l"(src));
}

// token -> element offset in [B,T,H,W,C] with cyclic shift (+4,+3,+3)
__device__ __forceinline__ int token_img_offset(int m) {
    int win = m / 392;
    int l   = m - win * 392;
    int b   = win >> 7;
    int w2  = win & 127;
    int it  = w2 >> 6, ih = (w2 >> 3) & 7, iw = w2 & 7;
    int lt  = l / 49; int r = l - lt * 49;
    int lh  = r / 7;  int lw = r - lh * 7;
    int t = (it * 8 + lt + 4) & 15;
    int h = ih * 7 + lh + 3; if (h >= 56) h -= 56;
    int w = iw * 7 + lw + 3; if (w >= 56) w -= 56;
    return (((b * 16 + t) * 56 + h) * 56 + w) * 128;
}

// ---------------------------------------------------------------------------
// Kernel 0: pre-pack bias (frag order, *log2e, 50 jt with -1e4 pad) + weights.
// ---------------------------------------------------------------------------
__global__ __launch_bounds__(256) void prep_kernel(
    const float* __restrict__ rpb, const float* __restrict__ qw,
    const float* __restrict__ pw)
{
    int i = blockIdx.x * 256 + threadIdx.x;
    const int NB = 4 * 25 * 50 * 32;          // 160000
    if (i < NB) {
        int lane = i & 31; int t = i >> 5;
        int jt = t % 50; t /= 50;
        int mt = t % 25; int h = t / 25;
        if (jt == 49) {
            g_rpbT[i] = make_float4(-1e4f, -1e4f, -1e4f, -1e4f);
        } else {
            int qr = mt * 16 + (lane >> 2);
            int qc0 = (qr < 392) ? qr : 391;
            int qc1 = (qr + 8 < 392) ? qr + 8 : 391;
            int jc = jt * 8 + 2 * (lane & 3);
            const float* bp = rpb + (size_t)h * (392 * 392);
            const float L2E = 1.4426950408889634f;
            float4 v;
            v.x = bp[(size_t)qc0 * 392 + jc] * L2E;
            v.y = bp[(size_t)qc0 * 392 + jc + 1] * L2E;
            v.z = bp[(size_t)qc1 * 392 + jc] * L2E;
            v.w = bp[(size_t)qc1 * 392 + jc + 1] * L2E;
            g_rpbT[i] = v;
        }
    } else if (i < NB + 384 * 128) {
        int k = i - NB;
        g_qwr[k] = u2f(rna(qw[k]));
    } else if (i < NB + 384 * 128 + 128 * 128) {
        int k = i - NB - 384 * 128;
        g_pwrh[k] = __float2half_rn(pw[k]);
    }
}

// ---------------------------------------------------------------------------
// 1xTF32 GEMM core: 128x128 tile, 512 thr, LDSM operands.
// ---------------------------------------------------------------------------
__device__ __forceinline__ void gemm1_core(
    float* As, float* Bs, int lane, int wm, int wn, float d[2][4][4])
{
    unsigned aoff = sptr(As + (wm * 32 + ((lane >> 3) & 1) * 8 + (lane & 7)) * 36
                            + ((lane >> 4) & 1) * 4);
    unsigned boff = sptr(Bs + (wn * 32 + ((lane >> 4) & 1) * 8 + (lane & 7)) * 36
                            + ((lane >> 3) & 1) * 4);
    const unsigned R16 = 16 * 36 * 4;

    #pragma unroll
    for (int ks = 0; ks < 4; ks++) {
        unsigned ka = ks * 32;
        unsigned a[2][4], b[2][4];
        ldsm4(a[0], aoff + ka);  ldsm4(a[1], aoff + ka + R16);
        ldsm4(b[0], boff + ka);  ldsm4(b[1], boff + ka + R16);
        #pragma unroll
        for (int mi = 0; mi < 2; mi++)
            #pragma unroll
            for (int p = 0; p < 2; p++) {
                mma8(d[mi][2 * p],     a[mi], b[p]);
                mma8(d[mi][2 * p + 1], a[mi], b[p] + 2);
            }
    }
}

// ---------------------------------------------------------------------------
// Kernel 1: QKV GEMM (tf32), cp.async double-buffered, fused gather,
// fp16 output. grid (3, 784).
// ---------------------------------------------------------------------------
__global__ __launch_bounds__(512, 2) void qkv_kernel(
    const float* __restrict__ x, const float* __restrict__ bias)
{
    extern __shared__ float sm[];
    float* Abuf = sm;                 // [2][128*36]
    float* Bbuf = sm + 2 * 4608;      // [2][128*36]
    int* rowsrc = (int*)(sm + 4 * 4608);

    int m0 = blockIdx.y * 128, n0 = blockIdx.x * 128;
    int tid = threadIdx.x;
    if (tid < 128) rowsrc[tid] = token_img_offset(m0 + tid);
    __syncthreads();

    int lane = tid & 31, warp = tid >> 5;
    int wm = warp >> 2, wn = warp & 3;

    float d[2][4][4];
    #pragma unroll
    for (int mi = 0; mi < 2; mi++)
        #pragma unroll
        for (int nj = 0; nj < 4; nj++)
            #pragma unroll
            for (int r = 0; r < 4; r++) d[mi][nj][r] = 0.f;

    int r0 = tid >> 3, f40 = (tid & 7) * 4;
    int r1 = (tid + 512) >> 3;

    {
        cpa16(sptr(Abuf + r0 * 36 + f40), x + rowsrc[r0] + f40);
        cpa16(sptr(Bbuf + r0 * 36 + f40), g_qwr + (size_t)(n0 + r0) * 128 + f40);
        cpa16(sptr(Abuf + r1 * 36 + f40), x + rowsrc[r1] + f40);
        cpa16(sptr(Bbuf + r1 * 36 + f40), g_qwr + (size_t)(n0 + r1) * 128 + f40);
        asm volatile("cp.async.commit_group;");
    }
    #pragma unroll
    for (int kc = 0; kc < 4; kc++) {
        if (kc < 3) {
            int bi = (kc + 1) & 1, kof = (kc + 1) * 32;
            cpa16(sptr(Abuf + bi * 4608 + r0 * 36 + f40), x + rowsrc[r0] + kof + f40);
            cpa16(sptr(Bbuf + bi * 4608 + r0 * 36 + f40), g_qwr + (size_t)(n0 + r0) * 128 + kof + f40);
            cpa16(sptr(Abuf + bi * 4608 + r1 * 36 + f40), x + rowsrc[r1] + kof + f40);
            cpa16(sptr(Bbuf + bi * 4608 + r1 * 36 + f40), g_qwr + (size_t)(n0 + r1) * 128 + kof + f40);
            asm volatile("cp.async.commit_group;");
            asm volatile("cp.async.wait_group 1;");
        } else {
            asm volatile("cp.async.wait_group 0;");
        }
        __syncthreads();
        gemm1_core(Abuf + (kc & 1) * 4608, Bbuf + (kc & 1) * 4608, lane, wm, wn, d);
        __syncthreads();
    }

    #pragma unroll
    for (int mi = 0; mi < 2; mi++) {
        int row = m0 + wm * 32 + mi * 16 + (lane >> 2);
        #pragma unroll
        for (int nj = 0; nj < 4; nj++) {
            int col = n0 + wn * 32 + nj * 8 + (lane & 3) * 2;
            float sc = (col < 128) ? 0.25503486f : 1.0f;   // hd^-0.5 * log2e
            float2 bv = *(const float2*)(bias + col);
            __half2 h0 = __floats2half2_rn((d[mi][nj][0] + bv.x) * sc,
                                           (d[mi][nj][1] + bv.y) * sc);
            __half2 h1 = __floats2half2_rn((d[mi][nj][2] + bv.x) * sc,
                                           (d[mi][nj][3] + bv.y) * sc);
            *(__half2*)(g_qkvh + (size_t)row * 384 + col) = h0;
            *(__half2*)(g_qkvh + (size_t)(row + 8) * 384 + col) = h1;
        }
    }
}

// ---------------------------------------------------------------------------
// Attention per-warp core (fp16 m16n8k16), templated on mask presence.
// exp via ex2.approx.f16x2; row sums via all-ones constant B fragment.
// ---------------------------------------------------------------------------
template<bool MASKED>
__device__ __forceinline__ void attn_tile(
    int mt, int lane, int win, int head,
    const __half* qbaseh, const unsigned char* rid,
    unsigned ksb, unsigned vtb)
{
    int qr = mt * 16 + (lane >> 2);
    int qc0 = (qr < 392) ? qr : 391;
    int qc1 = (qr + 8 < 392) ? (qr + 8) : 391;

    // Q A-fragments (2 x k16): raw fp16 pairs straight from gmem
    unsigned aq[2][4];
    {
        const unsigned* q0p = (const unsigned*)(qbaseh + (size_t)qc0 * 384) + (lane & 3);
        const unsigned* q1p = (const unsigned*)(qbaseh + (size_t)qc1 * 384) + (lane & 3);
        #pragma unroll
        for (int kk = 0; kk < 2; kk++) {
            aq[kk][0] = __ldg(q0p + kk * 8);
            aq[kk][1] = __ldg(q1p + kk * 8);
            aq[kk][2] = __ldg(q0p + kk * 8 + 4);
            aq[kk][3] = __ldg(q1p + kk * 8 + 4);
        }
    }

    unsigned char rq0 = 0, rq1 = 0;
    if (MASKED) { rq0 = rid[qc0]; rq1 = rid[qc1]; }
    const float4* bb = g_rpbT + ((head * 25 + mt) * 50) * 32 + lane;

    float oacc[4][4];
    #pragma unroll
    for (int dt = 0; dt < 4; dt++)
        #pragma unroll
        for (int r = 0; r < 4; r++) oacc[dt][r] = 0.f;
    float rsacc[4] = {0.f, 0.f, 0.f, 0.f};
    const unsigned onesb[2] = {0x3C003C00u, 0x3C003C00u};   // fp16 1.0 x4

    float4 bvA = __ldg(bb);
    float4 bvB = __ldg(bb + 32);

    #pragma unroll 2
    for (int p = 0; p < 25; p++) {
        float4 nA, nB;
        if (p < 24) {
            nA = __ldg(bb + (2 * p + 2) * 32);
            nB = __ldg(bb + (2 * p + 3) * 32);
        }
        // S accumulators init with (masked) bias
        float sA[4], sB[4];
        if (MASKED) {
            int jc = p * 16 + 2 * (lane & 3);
            unsigned char ra0 = rid[jc], ra1 = rid[jc + 1];
            unsigned char rb0 = rid[jc + 8], rb1 = rid[jc + 9];
            sA[0] = (rq0 == ra0) ? bvA.x : -1e4f;
            sA[1] = (rq0 == ra1) ? bvA.y : -1e4f;
            sA[2] = (rq1 == ra0) ? bvA.z : -1e4f;
            sA[3] = (rq1 == ra1) ? bvA.w : -1e4f;
            sB[0] = (rq0 == rb0) ? bvB.x : -1e4f;
            sB[1] = (rq0 == rb1) ? bvB.y : -1e4f;
            sB[2] = (rq1 == rb0) ? bvB.z : -1e4f;
            sB[3] = (rq1 == rb1) ? bvB.w : -1e4f;
        } else {
            sA[0] = bvA.x; sA[1] = bvA.y; sA[2] = bvA.z; sA[3] = bvA.w;
            sB[0] = bvB.x; sB[1] = bvB.y; sB[2] = bvB.z; sB[3] = bvB.w;
        }
        // S = Q K^T for the two 8-j tiles of this 16-j window
        unsigned kbA = ksb + (unsigned)p * 1280;     // 16 rows * 80 B
        unsigned b0[4], b1[4];
        ldsm4(b0, kbA);
        ldsm4(b1, kbA + 640);                        // +8 rows
        mmah(sA, aq[0], b0); mmah(sA, aq[1], b0 + 2);
        mmah(sB, aq[0], b1); mmah(sB, aq[1], b1 + 2);
        // pack exponents to fp16, exp2 in fp16 (P = A-fragment directly)
        unsigned pa[4];
        pa[0] = ex2h2(h2u(sA[0], sA[1]));
        pa[1] = ex2h2(h2u(sA[2], sA[3]));
        pa[2] = ex2h2(h2u(sB[0], sB[1]));
        pa[3] = ex2h2(h2u(sB[2], sB[3]));
        // PV: P(16x16) x V(16x32) + tensor-core row sums
        unsigned vb = vtb + (unsigned)p * 32;
        unsigned v0[4], v1[4];
        ldsm4(v0, vb);
        ldsm4(v1, vb + 16 * 816);                    // d 16..31
        mmah(oacc[0], pa, v0); mmah(oacc[1], pa, v0 + 2);
        mmah(oacc[2], pa, v1); mmah(oacc[3], pa, v1 + 2);
        mmah(rsacc, pa, onesb);                      // row sums (all cols equal)
        bvA = nA; bvB = nB;
    }

    float si0 = 1.f / rsacc[0];
    float si1 = 1.f / rsacc[2];

    size_t ob = ((size_t)win * 392 + qr) * 128 + head * 32;
    #pragma unroll
    for (int dt = 0; dt < 4; dt++) {
        int dc = dt * 8 + 2 * (lane & 3);
        *(__half2*)(g_atth + ob + dc) =
            __floats2half2_rn(oacc[dt][0] * si0, oacc[dt][1] * si0);
        if (qr + 8 < 392) {
            *(__half2*)(g_atth + ob + 8 * 128 + dc) =
                __floats2half2_rn(oacc[dt][2] * si1, oacc[dt][3] * si1);
        }
    }
}

// ---------------------------------------------------------------------------
// Kernel 2: single-pass flash attention (fp16). 416 thr (13 warps), 1 sync.
// Smem: Ksh[400][40]h | Vth[32][408]h | rid[400]  = 58,512 B -> 2 blocks/SM
// ---------------------------------------------------------------------------
__global__ __launch_bounds__(416, 2) void attn_kernel()
{
    extern __shared__ __align__(16) char smc[];
    __half* Ksh = (__half*)smc;                      // 32,000 B
    __half* Vth = (__half*)(smc + 32000);            // 26,112 B
    unsigned char* rid = (unsigned char*)(smc + 32000 + 26112);  // 400

    int bx = blockIdx.x;
    int win = bx >> 2, head = bx & 3;
    int tid = threadIdx.x;

    const __half* qbaseh = g_qkvh + (size_t)win * (392 * 384) + head * 32;
    const __half* kbaseh = qbaseh + 128;
    const __half* vbaseh = qbaseh + 256;

    int w2 = win & 127;
    int bt = ((w2 >> 6) == 1), bh = (((w2 >> 3) & 7) == 7), bw = ((w2 & 7) == 7);
    bool masked = bt || bh || bw;
    for (int l = tid; l < 400; l += 416) {
        unsigned char v = 255;
        if (l < 392) {
            int lt = l / 49; int r = l - lt * 49; int lh = r / 7; int lw = r - lh * 7;
            int rt = bt ? ((lt < 4) ? 1 : 2) : 0;
            int rh = bh ? ((lh < 4) ? 1 : 2) : 0;
            int rw = bw ? ((lw < 4) ? 1 : 2) : 0;
            v = (unsigned char)(rt * 9 + rh * 3 + rw);
        }
        rid[l] = v;
    }
    // K rows: straight fp16 copy, 16B vectors (pad rows 392..399 = 0)
    for (int i = tid; i < 400 * 4; i += 416) {
        int j = i >> 2, c = i & 3;                   // c: 8-half chunk
        uint4 v = (j < 392) ? *(const uint4*)(kbaseh + (size_t)j * 384 + c * 8)
                            : make_uint4(0, 0, 0, 0);
        *(uint4*)(Ksh + j * 40 + c * 8) = v;
    }
    // V transposed fp16 (pad j 392..407 = 0); half2 loads, 2 scalar stores
    for (int i = tid; i < 16 * 408; i += 416) {
        int d2 = i / 408, j = i - d2 * 408;
        __half2 hv = (j < 392) ? *(const __half2*)(vbaseh + (size_t)j * 384 + d2 * 2)
                               : __floats2half2_rn(0.f, 0.f);
        Vth[(2 * d2) * 408 + j]     = __low2half(hv);
        Vth[(2 * d2 + 1) * 408 + j] = __high2half(hv);
    }
    __syncthreads();   // the only block-wide sync

    int lane = tid & 31, warp = tid >> 5;
    unsigned ksb = sptr(Ksh) + (lane & 7) * 80 + (lane >> 3) * 16;
    unsigned vtb = sptr(Vth) + (((lane >> 4) & 1) * 8 + (lane & 7)) * 816
                             + ((lane >> 3) & 1) * 16;

    if (masked) {
        for (int mt = warp; mt < 25; mt += 13)
            attn_tile<true>(mt, lane, win, head, qbaseh, rid, ksb, vtb);
    } else {
        for (int mt = warp; mt < 25; mt += 13)
            attn_tile<false>(mt, lane, win, head, qbaseh, rid, ksb, vtb);
    }
}

// ---------------------------------------------------------------------------
// Kernel 3: proj GEMM (fp16), single-stage K=128, 2 syncs, fused scatter.
// Smem: Ah[128][136]h | Bh[128][136]h | rowdst  = 70,144 B
// ---------------------------------------------------------------------------
__global__ __launch_bounds__(512) void proj_kernel(
    const float* __restrict__ bias, float* __restrict__ out)
{
    extern __shared__ __align__(16) char smc[];
    __half* Ah = (__half*)smc;                       // 128*136 halves
    __half* Bh = (__half*)(smc + 34816);
    int* rowdst = (int*)(smc + 69632);

    int m0 = blockIdx.x * 128;
    int tid = threadIdx.x;
    if (tid < 128) rowdst[tid] = token_img_offset(m0 + tid);

    // load full K=128: 2048 16B chunks each for A and B
    for (int i = tid; i < 2048; i += 512) {
        int r = i >> 4, c = i & 15;
        cpa16(sptr(Ah + r * 136 + c * 8), g_atth + (size_t)(m0 + r) * 128 + c * 8);
        cpa16(sptr(Bh + r * 136 + c * 8), g_pwrh + (size_t)r * 128 + c * 8);
    }
    asm volatile("cp.async.commit_group;");
    asm volatile("cp.async.wait_group 0;");
    __syncthreads();

    int lane = tid & 31, warp = tid >> 5;
    int wm = warp >> 2, wn = warp & 3;

    float d[2][4][4];
    #pragma unroll
    for (int mi = 0; mi < 2; mi++)
        #pragma unroll
        for (int nj = 0; nj < 4; nj++)
            #pragma unroll
            for (int r = 0; r < 4; r++) d[mi][nj][r] = 0.f;

    unsigned aoff = sptr(Ah) + ((wm * 32 + (lane & 15)) * 136) * 2 + ((lane >> 4) & 1) * 16;
    unsigned boff = sptr(Bh) + ((wn * 32 + (lane & 7)) * 136) * 2 + (lane >> 3) * 16;
    const unsigned AR16 = 16 * 136 * 2;
    const unsigned BR8  = 8 * 136 * 2;

    #pragma unroll
    for (int ks = 0; ks < 4; ks++) {       // k32 chunks
        unsigned ka = ks * 64;
        unsigned a[2][2][4];               // [mi][kk16]
        #pragma unroll
        for (int mi = 0; mi < 2; mi++) {
            ldsm4(a[mi][0], aoff + mi * AR16 + ka);
            ldsm4(a[mi][1], aoff + mi * AR16 + ka + 32);
        }
        #pragma unroll
        for (int nj = 0; nj < 4; nj++) {
            unsigned b[4];                 // k32 for 8 n-rows
            ldsm4(b, boff + nj * BR8 + ka);
            #pragma unroll
            for (int mi = 0; mi < 2; mi++) {
                mmah(d[mi][nj], a[mi][0], b);
                mmah(d[mi][nj], a[mi][1], b + 2);
            }
        }
    }

    #pragma unroll
    for (int mi = 0; mi < 2; mi++) {
        int ml = wm * 32 + mi * 16 + (lane >> 2);
        #pragma unroll
        for (int nj = 0; nj < 4; nj++) {
            int col = wn * 32 + nj * 8 + (lane & 3) * 2;
            float2 bvv = *(const float2*)(bias + col);
            float2 o0, o1;
            o0.x = d[mi][nj][0] + bvv.x; o0.y = d[mi][nj][1] + bvv.y;
            o1.x = d[mi][nj][2] + bvv.x; o1.y = d[mi][nj][3] + bvv.y;
            *(float2*)(out + rowdst[ml] + col) = o0;
            *(float2*)(out + rowdst[ml + 8] + col) = o1;
        }
    }
}

// ---------------------------------------------------------------------------
extern "C" void kernel_launch(void* const* d_in, const int* in_sizes, int n_in,
                              void* d_out, int out_size)
{
    const float* x   = (const float*)d_in[0];
    const float* qw  = (const float*)d_in[1];
    const float* qb  = (const float*)d_in[2];
    const float* pw  = (const float*)d_in[3];
    const float* pb  = (const float*)d_in[4];
    const float* rpb = (const float*)d_in[5];
    float* out = (float*)d_out;

    const int smemG = 4 * 4608 * 4 + 512;    // 74,240 B
    const int smemA = 32000 + 26112 + 400;   // 58,512 B
    const int smemP = 69632 + 512;           // 70,144 B

    cudaFuncSetAttribute(qkv_kernel,  cudaFuncAttributeMaxDynamicSharedMemorySize, smemG);
    cudaFuncSetAttribute(attn_kernel, cudaFuncAttributeMaxDynamicSharedMemorySize, smemA);
    cudaFuncSetAttribute(proj_kernel, cudaFuncAttributeMaxDynamicSharedMemorySize, smemP);

    prep_kernel<<<881, 256>>>(rpb, qw, pw);
    qkv_kernel<<<dim3(3, 784), 512, smemG>>>(x, qb);
    attn_kernel<<<1024, 416, smemA>>>();
    proj_kernel<<<784, 512, smemP>>>(pb, out);
}